// round 1
// baseline (speedup 1.0000x reference)
#include <cuda_runtime.h>
#include <cuda_bf16.h>

// Fixed problem shapes (from reference setup_inputs):
//   C=16, H=16, W=16, O=32, KH=KW=3, stride 1, pad 1
//   N_in = 4096, N_out = 8192
// d_out layout (float32, tuple flattened in order):
//   [0      : 8192 )  x_out
//   [8192   : 16384)  lb_new
//   [16384  : 24576)  ub_new
//   [24576  : 24576+4096*8192) weights (row-major [4096, 8192])
//   [33579008 : 33587200) bias_vec
//
// weights[(c,hi,wi),(o,y,x)] = K[o,c,hi-y+1,wi-x+1] when in kernel window, else 0.

#define OFF_LB   8192
#define OFF_UB   16384
#define OFF_W    24576
#define OFF_BV   33579008

// ---------------------------------------------------------------------------
// Kernel A: interval-propagation convs + concrete forward + bias_vec.
// 32 blocks (one per output channel o) x 256 threads (one per (y,x)).
// ---------------------------------------------------------------------------
__global__ void __launch_bounds__(256) dp_conv_small(
    const float* __restrict__ x,
    const float* __restrict__ lb,
    const float* __restrict__ ub,
    const float* __restrict__ kern,   // [32,16,3,3]
    const float* __restrict__ bias,   // [32]
    float* __restrict__ out)
{
    __shared__ float sx[4096];
    __shared__ float slb[4096];
    __shared__ float sub[4096];
    __shared__ float sw[16 * 9];

    const int o = blockIdx.x;
    const int t = threadIdx.x;

    #pragma unroll
    for (int i = t; i < 4096; i += 256) {
        sx[i]  = x[i];
        slb[i] = lb[i];
        sub[i] = ub[i];
    }
    if (t < 144) sw[t] = kern[o * 144 + t];
    __syncthreads();

    const int y  = t >> 4;
    const int xx = t & 15;

    float xv = 0.f, lbv = 0.f, ubv = 0.f;

    for (int c = 0; c < 16; ++c) {
        #pragma unroll
        for (int kh = 0; kh < 3; ++kh) {
            const int hi = y + kh - 1;
            if ((unsigned)hi >= 16u) continue;
            #pragma unroll
            for (int kw = 0; kw < 3; ++kw) {
                const int wi = xx + kw - 1;
                if ((unsigned)wi >= 16u) continue;
                const float w  = sw[c * 9 + kh * 3 + kw];
                const int   ii = c * 256 + hi * 16 + wi;
                const float xin = sx[ii];
                const float lbi = slb[ii];
                const float ubi = sub[ii];
                xv += w * xin;
                if (w >= 0.f) { lbv += w * lbi; ubv += w * ubi; }
                else          { lbv += w * ubi; ubv += w * lbi; }
            }
        }
    }

    const float b  = bias[o];
    const int   oi = o * 256 + t;
    out[oi]           = xv  + b;
    out[OFF_LB + oi]  = lbv + 3.f * b;
    out[OFF_UB + oi]  = ubv + 3.f * b;
    out[OFF_BV + oi]  = b;
}

// ---------------------------------------------------------------------------
// Kernel B: fill the unrolled conv matrix [4096 x 8192] with float4 stores.
// One float4 per thread covers cols (o,y,x0..x0+3), x0 in {0,4,8,12}.
// Zero fast-path covers >96% of elements.
// ---------------------------------------------------------------------------
__global__ void __launch_bounds__(256) dp_fill_weights(
    const float* __restrict__ kern,   // [32,16,3,3]
    float4* __restrict__ wout)        // 8,388,608 float4s
{
    const unsigned idx = blockIdx.x * 256u + threadIdx.x;  // float4 index
    const unsigned n = idx >> 11;      // row 0..4095
    const unsigned j = idx & 2047u;    // float4-col 0..2047

    const int c  = (int)(n >> 8);
    const int hi = (int)((n >> 4) & 15u);
    const int wi = (int)(n & 15u);

    const unsigned m = j << 2;         // element col
    const int o  = (int)(m >> 8);
    const int y  = (int)((m >> 4) & 15u);
    const int x0 = (int)(m & 15u);

    float4 v = make_float4(0.f, 0.f, 0.f, 0.f);

    const int dy = hi - y + 1;          // valid 0..2
    if ((unsigned)dy < 3u) {
        const int dx0 = wi - x0 + 1;    // dx for lane t is dx0 - t; valid 0..2
        // overlap check: need dx0 - t in [0,2] for some t in [0,3]
        if (dx0 >= 0 && dx0 <= 5) {
            const float* kb = kern + (((o * 16 + c) * 3 + dy) * 3);
            if ((unsigned)(dx0    ) < 3u) v.x = __ldg(kb + dx0);
            if ((unsigned)(dx0 - 1) < 3u) v.y = __ldg(kb + dx0 - 1);
            if ((unsigned)(dx0 - 2) < 3u) v.z = __ldg(kb + dx0 - 2);
            if ((unsigned)(dx0 - 3) < 3u) v.w = __ldg(kb + dx0 - 3);
        }
    }
    wout[idx] = v;
}

extern "C" void kernel_launch(void* const* d_in, const int* in_sizes, int n_in,
                              void* d_out, int out_size)
{
    const float* x    = (const float*)d_in[0];
    const float* lb   = (const float*)d_in[1];
    const float* ub   = (const float*)d_in[2];
    // d_in[3] = input_shape (int32) — shapes are compile-time constants here
    const float* kern = (const float*)d_in[4];
    const float* bias = (const float*)d_in[5];
    float* out = (float*)d_out;

    dp_conv_small<<<32, 256>>>(x, lb, ub, kern, bias, out);

    // 4096*8192/4 = 8,388,608 float4 stores -> 32768 blocks of 256
    dp_fill_weights<<<32768, 256>>>(kern, (float4*)(out + OFF_W));
}

// round 3
// speedup vs baseline: 1.2910x; 1.2910x over previous
#include <cuda_runtime.h>
#include <cuda_bf16.h>

// Fixed problem shapes: C=16, H=W=16, O=32, KH=KW=3, stride 1, pad 1
// N_in = 4096, N_out = 8192
// d_out layout (float32):
//   [0      : 8192 )            x_out
//   [8192   : 16384)            lb_new
//   [16384  : 24576)            ub_new
//   [24576  : 24576+4096*8192)  weights [4096, 8192] row-major
//   [33579008 : 33587200)       bias_vec
//
// weights[(c,hi,wi),(o,y,x)] = K[o,c,hi-y+1,wi-x+1] when |hi-y|<=1 && |wi-x|<=1, else 0.

#define OFF_LB   8192u
#define OFF_UB   16384u
#define OFF_W    24576u
#define OFF_BV   33579008u

#define CONV_BLOCKS 32
#define FILL_BLOCKS 8192           // each fills 1024 float4 = 16KB = half a row
#define TOTAL_BLOCKS (CONV_BLOCKS + FILL_BLOCKS)

__global__ void __launch_bounds__(256) dp_merged(
    const float* __restrict__ x,
    const float* __restrict__ lb,
    const float* __restrict__ ub,
    const float* __restrict__ kern,   // [32,16,3,3] = [32][144]
    const float* __restrict__ bias,   // [32]
    float* __restrict__ out)
{
    const int b = blockIdx.x;
    const int t = threadIdx.x;

    if (b >= CONV_BLOCKS) {
        // ------------------------------------------------------------------
        // FILL path: zero a 1024-float4 tile (half of one matrix row), then
        // overwrite the <=144 nonzero band entries of this half-row.
        // ------------------------------------------------------------------
        const unsigned tile = (unsigned)(b - CONV_BLOCKS);     // 0..8191
        float4* __restrict__ w4 = (float4*)(out + OFF_W);

        const unsigned f0 = tile * 1024u + (unsigned)t;
        const float4 z = make_float4(0.f, 0.f, 0.f, 0.f);
        w4[f0]        = z;
        w4[f0 + 256u] = z;
        w4[f0 + 512u] = z;
        w4[f0 + 768u] = z;

        __syncthreads();   // order zero-stores before band overwrites (same block)

        if (t < 144) {
            const unsigned n  = tile >> 1;          // row 0..4095
            const unsigned h  = tile & 1u;          // which 16-o half
            const int c  = (int)(n >> 8);
            const int hi = (int)((n >> 4) & 15u);
            const int wi = (int)(n & 15u);

            const int ol  = t / 9;                  // 0..15
            const int rem = t - ol * 9;
            const int dyy = rem / 3;                // 0..2 : y = hi-1+dyy
            const int d   = rem - dyy * 3;          // 0..2 : x = wi-1+d

            const int o  = (int)(h * 16u) + ol;     // 0..31
            const int y  = hi - 1 + dyy;
            const int xx = wi - 1 + d;
            if ((unsigned)y < 16u && (unsigned)xx < 16u) {
                // kernel tap: kh = hi-y+1 = 2-dyy, kw = wi-xx+1 = 2-d
                const float kv = __ldg(kern + ((o * 16 + c) * 9 + (2 - dyy) * 3 + (2 - d)));
                out[OFF_W + n * 8192u + (unsigned)(o * 256 + y * 16 + xx)] = kv;
            }
        }
        return;
    }

    // ----------------------------------------------------------------------
    // CONV path: block b = output channel o. One thread per (y,x).
    // ----------------------------------------------------------------------
    __shared__ float sw[144];
    const int o = b;
    if (t < 144) sw[t] = kern[o * 144 + t];
    __syncthreads();

    const int y  = t >> 4;
    const int xx = t & 15;

    float xv = 0.f, lbv = 0.f, ubv = 0.f;

    #pragma unroll 4
    for (int c = 0; c < 16; ++c) {
        #pragma unroll
        for (int kh = 0; kh < 3; ++kh) {
            const int hi = y + kh - 1;
            if ((unsigned)hi >= 16u) continue;
            #pragma unroll
            for (int kw = 0; kw < 3; ++kw) {
                const int wi = xx + kw - 1;
                if ((unsigned)wi >= 16u) continue;
                const float w  = sw[c * 9 + kh * 3 + kw];
                const int   ii = c * 256 + hi * 16 + wi;
                const float xin = __ldg(x  + ii);
                const float lbi = __ldg(lb + ii);
                const float ubi = __ldg(ub + ii);
                xv += w * xin;
                if (w >= 0.f) { lbv += w * lbi; ubv += w * ubi; }
                else          { lbv += w * ubi; ubv += w * lbi; }
            }
        }
    }

    const float bv = __ldg(bias + o);
    const unsigned oi = (unsigned)(o * 256 + t);
    out[oi]           = xv  + bv;
    out[OFF_LB + oi]  = lbv + 3.f * bv;
    out[OFF_UB + oi]  = ubv + 3.f * bv;
    out[OFF_BV + oi]  = bv;
}

extern "C" void kernel_launch(void* const* d_in, const int* in_sizes, int n_in,
                              void* d_out, int out_size)
{
    const float* x    = (const float*)d_in[0];
    const float* lb   = (const float*)d_in[1];
    const float* ub   = (const float*)d_in[2];
    // d_in[3] = input_shape (int32) — compile-time constants here
    const float* kern = (const float*)d_in[4];
    const float* bias = (const float*)d_in[5];
    float* out = (float*)d_out;

    dp_merged<<<TOTAL_BLOCKS, 256>>>(x, lb, ub, kern, bias, out);
}